// round 1
// baseline (speedup 1.0000x reference)
#include <cuda_runtime.h>
#include <math.h>

#define B_   2
#define T_   2048
#define S_   2048
#define E_   1024
#define H_   16
#define DH_  64
#define SCALE_ 0.125f
#define CLAMP_V 50000.0f

// Scratch (device globals: no allocations allowed)
__device__ float g_Qp[B_ * T_ * E_];
__device__ float g_Kp[B_ * S_ * E_];
__device__ float g_Vp[B_ * S_ * E_];
__device__ float g_ctx[B_ * T_ * E_];

// ---------------------------------------------------------------------------
// NT GEMM with bias + alpha: C[m,n] = alpha * (sum_k A[m,k]*B[n,k] + bias[n])
// Tiles: 64x64 output, BK=16. 256 threads, 4x4 register microtile per thread.
// ---------------------------------------------------------------------------
__global__ __launch_bounds__(256) void gemm_nt_bias(
    const float* __restrict__ A, const float* __restrict__ Bm,
    const float* __restrict__ bias, float* __restrict__ C,
    int K, int lda, int ldb, int ldc, float alpha)
{
    __shared__ float As[16][68];
    __shared__ float Bs[16][68];
    const int tid  = threadIdx.x;
    const int tx   = tid & 15;
    const int ty   = tid >> 4;
    const int bm   = blockIdx.y * 64;
    const int bn   = blockIdx.x * 64;
    const int lrow = tid >> 2;          // 0..63
    const int lk   = (tid & 3) << 2;    // 0,4,8,12

    const float* Aptr = A + (size_t)(bm + lrow) * lda + lk;
    const float* Bptr = Bm + (size_t)(bn + lrow) * ldb + lk;

    float acc[4][4] = {};

    for (int k0 = 0; k0 < K; k0 += 16) {
        float4 a4 = *(const float4*)(Aptr + k0);
        float4 b4 = *(const float4*)(Bptr + k0);
        __syncthreads();
        As[lk + 0][lrow] = a4.x; As[lk + 1][lrow] = a4.y;
        As[lk + 2][lrow] = a4.z; As[lk + 3][lrow] = a4.w;
        Bs[lk + 0][lrow] = b4.x; Bs[lk + 1][lrow] = b4.y;
        Bs[lk + 2][lrow] = b4.z; Bs[lk + 3][lrow] = b4.w;
        __syncthreads();
#pragma unroll
        for (int kk = 0; kk < 16; kk++) {
            float4 av = *(const float4*)&As[kk][ty * 4];
            float4 bv = *(const float4*)&Bs[kk][tx * 4];
            float a[4] = {av.x, av.y, av.z, av.w};
            float b[4] = {bv.x, bv.y, bv.z, bv.w};
#pragma unroll
            for (int i = 0; i < 4; i++)
#pragma unroll
                for (int j = 0; j < 4; j++)
                    acc[i][j] += a[i] * b[j];
        }
    }

#pragma unroll
    for (int i = 0; i < 4; i++) {
        int row = bm + ty * 4 + i;
#pragma unroll
        for (int j = 0; j < 4; j++) {
            int col = bn + tx * 4 + j;
            C[(size_t)row * ldc + col] = alpha * (acc[i][j] + bias[col]);
        }
    }
}

// ---------------------------------------------------------------------------
// Scores: per (b,h): S[t,s] = clamp(Q[t,:].K[s,:]) with mask -> -inf
// Q already pre-scaled by SCALE_. Writes raw masked scores into attn region.
// ---------------------------------------------------------------------------
__global__ __launch_bounds__(256) void attn_scores(
    const float* __restrict__ Qp, const float* __restrict__ Kp,
    const int* __restrict__ mask, float* __restrict__ P)
{
    __shared__ float As[16][68];
    __shared__ float Bs[16][68];
    const int bh = blockIdx.z;
    const int b  = bh >> 4;
    const int h  = bh & 15;
    const float* A  = Qp + (size_t)b * T_ * E_ + h * DH_;
    const float* Bm = Kp + (size_t)b * S_ * E_ + h * DH_;
    float* C = P + (size_t)bh * T_ * S_;

    const int tid  = threadIdx.x;
    const int tx   = tid & 15;
    const int ty   = tid >> 4;
    const int bm   = blockIdx.y * 64;
    const int bn   = blockIdx.x * 64;
    const int lrow = tid >> 2;
    const int lk   = (tid & 3) << 2;

    const float* Aptr = A + (size_t)(bm + lrow) * E_ + lk;
    const float* Bptr = Bm + (size_t)(bn + lrow) * E_ + lk;

    float acc[4][4] = {};

    for (int k0 = 0; k0 < DH_; k0 += 16) {
        float4 a4 = *(const float4*)(Aptr + k0);
        float4 b4 = *(const float4*)(Bptr + k0);
        __syncthreads();
        As[lk + 0][lrow] = a4.x; As[lk + 1][lrow] = a4.y;
        As[lk + 2][lrow] = a4.z; As[lk + 3][lrow] = a4.w;
        Bs[lk + 0][lrow] = b4.x; Bs[lk + 1][lrow] = b4.y;
        Bs[lk + 2][lrow] = b4.z; Bs[lk + 3][lrow] = b4.w;
        __syncthreads();
#pragma unroll
        for (int kk = 0; kk < 16; kk++) {
            float4 av = *(const float4*)&As[kk][ty * 4];
            float4 bv = *(const float4*)&Bs[kk][tx * 4];
            float a[4] = {av.x, av.y, av.z, av.w};
            float bb[4] = {bv.x, bv.y, bv.z, bv.w};
#pragma unroll
            for (int i = 0; i < 4; i++)
#pragma unroll
                for (int j = 0; j < 4; j++)
                    acc[i][j] += a[i] * bb[j];
        }
    }

    const int* mrow = mask + (size_t)b * S_;
#pragma unroll
    for (int j = 0; j < 4; j++) {
        int col = bn + tx * 4 + j;
        bool keep = (mrow[col] != 0);
#pragma unroll
        for (int i = 0; i < 4; i++) {
            int row = bm + ty * 4 + i;
            float v = acc[i][j];
            v = fminf(fmaxf(v, -CLAMP_V), CLAMP_V);
            if (!keep) v = -INFINITY;
            C[(size_t)row * S_ + col] = v;
        }
    }
}

// ---------------------------------------------------------------------------
// Row softmax in place over last dim (S_=2048). 256 threads x 8 elems.
// ---------------------------------------------------------------------------
__global__ __launch_bounds__(256) void softmax_rows(float* __restrict__ P)
{
    float* row = P + (size_t)blockIdx.x * S_;
    const int tid = threadIdx.x;
    __shared__ float red[8];

    float vals[8];
    float m = -INFINITY;
#pragma unroll
    for (int i = 0; i < 8; i++) {
        vals[i] = row[tid + i * 256];
        m = fmaxf(m, vals[i]);
    }
#pragma unroll
    for (int o = 16; o; o >>= 1) m = fmaxf(m, __shfl_xor_sync(0xffffffffu, m, o));
    if ((tid & 31) == 0) red[tid >> 5] = m;
    __syncthreads();
    float m2 = red[0];
#pragma unroll
    for (int i = 1; i < 8; i++) m2 = fmaxf(m2, red[i]);
    __syncthreads();

    float s = 0.f;
#pragma unroll
    for (int i = 0; i < 8; i++) {
        vals[i] = __expf(vals[i] - m2);
        s += vals[i];
    }
#pragma unroll
    for (int o = 16; o; o >>= 1) s += __shfl_xor_sync(0xffffffffu, s, o);
    if ((tid & 31) == 0) red[tid >> 5] = s;
    __syncthreads();
    float tot = 0.f;
#pragma unroll
    for (int i = 0; i < 8; i++) tot += red[i];
    float inv = 1.f / tot;
#pragma unroll
    for (int i = 0; i < 8; i++) row[tid + i * 256] = vals[i] * inv;
}

// ---------------------------------------------------------------------------
// P @ V per (b,h): Ctx[t,d] = sum_s P[t,s] * V[s,d]. NN GEMM, N=64 (one tile).
// ---------------------------------------------------------------------------
__global__ __launch_bounds__(256) void attn_pv(
    const float* __restrict__ P, const float* __restrict__ Vp,
    float* __restrict__ Ctx)
{
    __shared__ float As[16][68];
    __shared__ float Bs[16][68];
    const int bh = blockIdx.z;
    const int b  = bh >> 4;
    const int h  = bh & 15;
    const float* A  = P + (size_t)bh * T_ * S_;
    const float* Bm = Vp + (size_t)b * S_ * E_ + h * DH_;
    float* C = Ctx + (size_t)b * T_ * E_ + h * DH_;

    const int tid  = threadIdx.x;
    const int tx   = tid & 15;
    const int ty   = tid >> 4;
    const int bm   = blockIdx.y * 64;
    const int lrow = tid >> 2;          // A loader: 0..63
    const int lk   = (tid & 3) << 2;
    const int krow = tid >> 4;          // B loader: 0..15
    const int ncol = (tid & 15) << 2;   // 0..60

    const float* Aptr = A + (size_t)(bm + lrow) * S_ + lk;

    float acc[4][4] = {};

    for (int k0 = 0; k0 < S_; k0 += 16) {
        float4 a4 = *(const float4*)(Aptr + k0);
        float4 b4 = *(const float4*)(Bm + (size_t)(k0 + krow) * E_ + ncol);
        __syncthreads();
        As[lk + 0][lrow] = a4.x; As[lk + 1][lrow] = a4.y;
        As[lk + 2][lrow] = a4.z; As[lk + 3][lrow] = a4.w;
        *(float4*)&Bs[krow][ncol] = b4;
        __syncthreads();
#pragma unroll
        for (int kk = 0; kk < 16; kk++) {
            float4 av = *(const float4*)&As[kk][ty * 4];
            float4 bv = *(const float4*)&Bs[kk][tx * 4];
            float a[4] = {av.x, av.y, av.z, av.w};
            float bb[4] = {bv.x, bv.y, bv.z, bv.w};
#pragma unroll
            for (int i = 0; i < 4; i++)
#pragma unroll
                for (int j = 0; j < 4; j++)
                    acc[i][j] += a[i] * bb[j];
        }
    }

#pragma unroll
    for (int i = 0; i < 4; i++) {
        int row = bm + ty * 4 + i;
#pragma unroll
        for (int j = 0; j < 4; j++) {
            int col = tx * 4 + j;
            C[(size_t)row * E_ + col] = acc[i][j];
        }
    }
}

// ---------------------------------------------------------------------------
extern "C" void kernel_launch(void* const* d_in, const int* in_sizes, int n_in,
                              void* d_out, int out_size)
{
    const float* q    = (const float*)d_in[0];
    const float* k    = (const float*)d_in[1];
    const float* v    = (const float*)d_in[2];
    const int*   mask = (const int*)d_in[3];
    const float* Wq   = (const float*)d_in[4];
    const float* bq   = (const float*)d_in[5];
    const float* Wk   = (const float*)d_in[6];
    const float* bk   = (const float*)d_in[7];
    const float* Wv   = (const float*)d_in[8];
    const float* bv   = (const float*)d_in[9];
    const float* Wo   = (const float*)d_in[10];
    const float* bo   = (const float*)d_in[11];

    float* out  = (float*)d_out;                         // [B,T,E] = 4194304
    float* attn = out + (size_t)B_ * T_ * E_;            // [B,H,T,S]

    float *Qp, *Kp, *Vp, *Ctx;
    cudaGetSymbolAddress((void**)&Qp, g_Qp);
    cudaGetSymbolAddress((void**)&Kp, g_Kp);
    cudaGetSymbolAddress((void**)&Vp, g_Vp);
    cudaGetSymbolAddress((void**)&Ctx, g_ctx);

    dim3 blk(256);
    dim3 gproj(E_ / 64, (B_ * T_) / 64);                 // 16 x 64

    // Projections (SCALE folded into Q)
    gemm_nt_bias<<<gproj, blk>>>(q, Wq, bq, Qp, E_, E_, E_, E_, SCALE_);
    gemm_nt_bias<<<gproj, blk>>>(k, Wk, bk, Kp, E_, E_, E_, E_, 1.0f);
    gemm_nt_bias<<<gproj, blk>>>(v, Wv, bv, Vp, E_, E_, E_, E_, 1.0f);

    // Scores (clamp + mask) written in-place into attn output region
    attn_scores<<<dim3(S_ / 64, T_ / 64, B_ * H_), blk>>>(Qp, Kp, mask, attn);

    // Row softmax in place
    softmax_rows<<<B_ * H_ * T_, blk>>>(attn);

    // Context = P @ V
    attn_pv<<<dim3(1, T_ / 64, B_ * H_), blk>>>(attn, Vp, Ctx);

    // Output projection
    gemm_nt_bias<<<gproj, blk>>>(Ctx, Wo, bo, out, E_, E_, E_, E_, 1.0f);
}

// round 2
// speedup vs baseline: 1.0979x; 1.0979x over previous
#include <cuda_runtime.h>
#include <math.h>

#define B_   2
#define T_   2048
#define S_   2048
#define E_   1024
#define H_   16
#define DH_  64
#define SCALE_ 0.125f
#define CLAMP_V 50000.0f
#define NBLK 16              // S_/128 score col-blocks per row

// Scratch (device globals: no allocations allowed)
__device__ float  g_Qp[B_ * T_ * E_];
__device__ float  g_Kp[B_ * S_ * E_];
__device__ float  g_Vp[B_ * S_ * E_];
__device__ float  g_ctx[B_ * T_ * E_];
__device__ float2 g_part[(size_t)B_ * H_ * T_ * NBLK];   // per-block (m, s)
__device__ float2 g_stats[(size_t)B_ * H_ * T_];         // per-row (m, 1/s)

__device__ __forceinline__ void stg_smem_t(float (*Sm)[132], int kbase, int row,
                                           float4 v0, float4 v1) {
    Sm[kbase + 0][row] = v0.x; Sm[kbase + 1][row] = v0.y;
    Sm[kbase + 2][row] = v0.z; Sm[kbase + 3][row] = v0.w;
    Sm[kbase + 4][row] = v1.x; Sm[kbase + 5][row] = v1.y;
    Sm[kbase + 6][row] = v1.z; Sm[kbase + 7][row] = v1.w;
}

// ---------------------------------------------------------------------------
// NT GEMM + bias + alpha: C[m,n] = alpha*(sum_k A[m,k]*B[n,k] + bias[n])
// 128x128 tile, BK=16, 256 threads, 8x8 microtile, double-buffered smem.
// ---------------------------------------------------------------------------
__global__ __launch_bounds__(256) void gemm_nt_bias(
    const float* __restrict__ A, const float* __restrict__ Bm,
    const float* __restrict__ bias, float* __restrict__ C,
    int K, int lda, int ldb, int ldc, float alpha)
{
    __shared__ float As[2][16][132];
    __shared__ float Bs[2][16][132];
    const int tid = threadIdx.x;
    const int tx = tid & 15, ty = tid >> 4;
    const int bm = blockIdx.y * 128, bn = blockIdx.x * 128;
    const int lrow = tid >> 1;
    const int lk   = (tid & 1) * 8;

    const float* Ap = A + (size_t)(bm + lrow) * lda + lk;
    const float* Bp = Bm + (size_t)(bn + lrow) * ldb + lk;

    float acc[8][8] = {};

    {   // prologue: tile 0 -> buf 0
        float4 a0 = *(const float4*)(Ap);
        float4 a1 = *(const float4*)(Ap + 4);
        float4 b0 = *(const float4*)(Bp);
        float4 b1 = *(const float4*)(Bp + 4);
        stg_smem_t(As[0], lk, lrow, a0, a1);
        stg_smem_t(Bs[0], lk, lrow, b0, b1);
    }
    __syncthreads();

    int buf = 0;
    for (int k0 = 0; k0 < K; k0 += 16) {
        const bool more = (k0 + 16) < K;
        float4 na0, na1, nb0, nb1;
        if (more) {
            na0 = *(const float4*)(Ap + k0 + 16);
            na1 = *(const float4*)(Ap + k0 + 20);
            nb0 = *(const float4*)(Bp + k0 + 16);
            nb1 = *(const float4*)(Bp + k0 + 20);
        }
#pragma unroll
        for (int kk = 0; kk < 16; kk++) {
            float4 av0 = *(const float4*)&As[buf][kk][ty * 8];
            float4 av1 = *(const float4*)&As[buf][kk][ty * 8 + 4];
            float4 bv0 = *(const float4*)&Bs[buf][kk][tx * 8];
            float4 bv1 = *(const float4*)&Bs[buf][kk][tx * 8 + 4];
            float a[8] = {av0.x, av0.y, av0.z, av0.w, av1.x, av1.y, av1.z, av1.w};
            float b[8] = {bv0.x, bv0.y, bv0.z, bv0.w, bv1.x, bv1.y, bv1.z, bv1.w};
#pragma unroll
            for (int i = 0; i < 8; i++)
#pragma unroll
                for (int j = 0; j < 8; j++)
                    acc[i][j] += a[i] * b[j];
        }
        if (more) {
            buf ^= 1;
            stg_smem_t(As[buf], lk, lrow, na0, na1);
            stg_smem_t(Bs[buf], lk, lrow, nb0, nb1);
            __syncthreads();
        }
    }

#pragma unroll
    for (int i = 0; i < 8; i++) {
        int row = bm + ty * 8 + i;
        float* cr = C + (size_t)row * ldc + bn + tx * 8;
        float4 o0, o1;
        o0.x = alpha * (acc[i][0] + bias[bn + tx * 8 + 0]);
        o0.y = alpha * (acc[i][1] + bias[bn + tx * 8 + 1]);
        o0.z = alpha * (acc[i][2] + bias[bn + tx * 8 + 2]);
        o0.w = alpha * (acc[i][3] + bias[bn + tx * 8 + 3]);
        o1.x = alpha * (acc[i][4] + bias[bn + tx * 8 + 4]);
        o1.y = alpha * (acc[i][5] + bias[bn + tx * 8 + 5]);
        o1.z = alpha * (acc[i][6] + bias[bn + tx * 8 + 6]);
        o1.w = alpha * (acc[i][7] + bias[bn + tx * 8 + 7]);
        *(float4*)(cr)     = o0;
        *(float4*)(cr + 4) = o1;
    }
}

// ---------------------------------------------------------------------------
// Scores: per (b,h), 128x128 tile of clamp(Q.K^T) with mask -> -inf, written
// raw to P. Also emits per-(row, colblock) online-softmax partials (m, s).
// ---------------------------------------------------------------------------
__global__ __launch_bounds__(256) void attn_scores(
    const float* __restrict__ Qp, const float* __restrict__ Kp,
    const int* __restrict__ mask, float* __restrict__ P,
    float2* __restrict__ part)
{
    __shared__ float As[2][16][132];
    __shared__ float Bs[2][16][132];
    const int bh = blockIdx.z;
    const int b  = bh >> 4;
    const int h  = bh & 15;
    const float* A  = Qp + (size_t)b * T_ * E_ + h * DH_;
    const float* Bm = Kp + (size_t)b * S_ * E_ + h * DH_;
    float* C = P + (size_t)bh * T_ * S_;

    const int tid = threadIdx.x;
    const int tx = tid & 15, ty = tid >> 4;
    const int bm = blockIdx.y * 128, bn = blockIdx.x * 128;
    const int lrow = tid >> 1;
    const int lk   = (tid & 1) * 8;

    const float* Ap = A + (size_t)(bm + lrow) * E_ + lk;
    const float* Bp = Bm + (size_t)(bn + lrow) * E_ + lk;

    float acc[8][8] = {};

    {
        float4 a0 = *(const float4*)(Ap);
        float4 a1 = *(const float4*)(Ap + 4);
        float4 b0 = *(const float4*)(Bp);
        float4 b1 = *(const float4*)(Bp + 4);
        stg_smem_t(As[0], lk, lrow, a0, a1);
        stg_smem_t(Bs[0], lk, lrow, b0, b1);
    }
    __syncthreads();

    int buf = 0;
    for (int k0 = 0; k0 < DH_; k0 += 16) {
        const bool more = (k0 + 16) < DH_;
        float4 na0, na1, nb0, nb1;
        if (more) {
            na0 = *(const float4*)(Ap + k0 + 16);
            na1 = *(const float4*)(Ap + k0 + 20);
            nb0 = *(const float4*)(Bp + k0 + 16);
            nb1 = *(const float4*)(Bp + k0 + 20);
        }
#pragma unroll
        for (int kk = 0; kk < 16; kk++) {
            float4 av0 = *(const float4*)&As[buf][kk][ty * 8];
            float4 av1 = *(const float4*)&As[buf][kk][ty * 8 + 4];
            float4 bv0 = *(const float4*)&Bs[buf][kk][tx * 8];
            float4 bv1 = *(const float4*)&Bs[buf][kk][tx * 8 + 4];
            float a[8] = {av0.x, av0.y, av0.z, av0.w, av1.x, av1.y, av1.z, av1.w};
            float bb[8] = {bv0.x, bv0.y, bv0.z, bv0.w, bv1.x, bv1.y, bv1.z, bv1.w};
#pragma unroll
            for (int i = 0; i < 8; i++)
#pragma unroll
                for (int j = 0; j < 8; j++)
                    acc[i][j] += a[i] * bb[j];
        }
        if (more) {
            buf ^= 1;
            stg_smem_t(As[buf], lk, lrow, na0, na1);
            stg_smem_t(Bs[buf], lk, lrow, nb0, nb1);
            __syncthreads();
        }
    }

    // mask bits for my 8 columns
    const int* mrow = mask + (size_t)b * S_;
    int4 mk0 = *(const int4*)&mrow[bn + tx * 8];
    int4 mk1 = *(const int4*)&mrow[bn + tx * 8 + 4];
    const bool keep[8] = {mk0.x != 0, mk0.y != 0, mk0.z != 0, mk0.w != 0,
                          mk1.x != 0, mk1.y != 0, mk1.z != 0, mk1.w != 0};

#pragma unroll
    for (int i = 0; i < 8; i++) {
        // clamp + mask
#pragma unroll
        for (int j = 0; j < 8; j++) {
            float v = fminf(fmaxf(acc[i][j], -CLAMP_V), CLAMP_V);
            acc[i][j] = keep[j] ? v : -INFINITY;
        }
        // write raw scores
        int row = bm + ty * 8 + i;
        float* cr = C + (size_t)row * S_ + bn + tx * 8;
        float4 o0 = {acc[i][0], acc[i][1], acc[i][2], acc[i][3]};
        float4 o1 = {acc[i][4], acc[i][5], acc[i][6], acc[i][7]};
        *(float4*)(cr)     = o0;
        *(float4*)(cr + 4) = o1;

        // local (m, s) over my 8 cols
        float m = -INFINITY;
#pragma unroll
        for (int j = 0; j < 8; j++) m = fmaxf(m, acc[i][j]);
        float s = 0.f;
        if (m != -INFINITY) {
#pragma unroll
            for (int j = 0; j < 8; j++) s += __expf(acc[i][j] - m);
        }
        // combine across the 16 lanes sharing this row (tx group in half-warp)
#pragma unroll
        for (int off = 8; off; off >>= 1) {
            float om = __shfl_xor_sync(0xffffffffu, m, off);
            float os = __shfl_xor_sync(0xffffffffu, s, off);
            float nm = fmaxf(m, om);
            s = (nm == -INFINITY) ? 0.f
                                  : s * __expf(m - nm) + os * __expf(om - nm);
            m = nm;
        }
        if (tx == 0)
            part[((size_t)bh * T_ + row) * NBLK + blockIdx.x] = make_float2(m, s);
    }
}

// ---------------------------------------------------------------------------
// Finalize row stats: combine NBLK partials -> (m, 1/s) per row.
// ---------------------------------------------------------------------------
__global__ __launch_bounds__(256) void stats_reduce(
    const float2* __restrict__ part, float2* __restrict__ stats)
{
    int r = blockIdx.x * 256 + threadIdx.x;     // 0 .. B*H*T-1
    float m = -INFINITY, s = 0.f;
#pragma unroll
    for (int j = 0; j < NBLK; j++) {
        float2 p = part[(size_t)r * NBLK + j];
        float nm = fmaxf(m, p.x);
        if (nm == -INFINITY) continue;
        s = s * __expf(m - nm) + p.y * __expf(p.x - nm);
        m = nm;
    }
    stats[r] = make_float2(m, 1.f / s);
}

// ---------------------------------------------------------------------------
// P@V per (b,h). Reads RAW scores, applies p = exp(v-m)*inv at load time,
// writes normalized p back to P (output) and uses p in the GEMM.
// BM=128, BN=64(=DH), BK=16, 256 threads, 8x4 microtile.
// ---------------------------------------------------------------------------
__global__ __launch_bounds__(256) void attn_pv(
    float* __restrict__ P, const float* __restrict__ Vp,
    const float2* __restrict__ stats, float* __restrict__ Ctx)
{
    __shared__ float As[2][16][132];
    __shared__ float Bs[2][16][68];
    const int bh = blockIdx.z;
    const int b  = bh >> 4;
    const int h  = bh & 15;
    float* A = P + (size_t)bh * T_ * S_;
    const float* Bm = Vp + (size_t)b * S_ * E_ + h * DH_;
    float* C = Ctx + (size_t)b * T_ * E_ + h * DH_;

    const int tid = threadIdx.x;
    const int tx = tid & 15, ty = tid >> 4;
    const int bm = blockIdx.y * 128;
    const int arow = tid >> 1;
    const int ak   = (tid & 1) * 8;
    const int brow = tid >> 4;
    const int bcol = (tid & 15) * 4;

    float* Aptr = A + (size_t)(bm + arow) * S_ + ak;
    const float* Bptr = Bm + (size_t)brow * E_ + bcol;

    float2 st = stats[(size_t)bh * T_ + bm + arow];
    const float mrow = st.x, inv = st.y;

    float acc[8][4] = {};

    {   // prologue
        float4 a0 = *(const float4*)(Aptr);
        float4 a1 = *(const float4*)(Aptr + 4);
        float4 b4 = *(const float4*)(Bptr);
        float p[8] = {a0.x, a0.y, a0.z, a0.w, a1.x, a1.y, a1.z, a1.w};
#pragma unroll
        for (int u = 0; u < 8; u++) p[u] = __expf(p[u] - mrow) * inv;
        float4 w0 = {p[0], p[1], p[2], p[3]};
        float4 w1 = {p[4], p[5], p[6], p[7]};
        *(float4*)(Aptr)     = w0;
        *(float4*)(Aptr + 4) = w1;
        stg_smem_t(As[0], ak, arow, w0, w1);
        *(float4*)&Bs[0][brow][bcol] = b4;
    }
    __syncthreads();

    int buf = 0;
    for (int k0 = 0; k0 < S_; k0 += 16) {
        const bool more = (k0 + 16) < S_;
        float4 w0, w1, nb;
        if (more) {
            float4 a0 = *(const float4*)(Aptr + k0 + 16);
            float4 a1 = *(const float4*)(Aptr + k0 + 20);
            nb = *(const float4*)(Bptr + (size_t)(k0 + 16) * E_);
            float p[8] = {a0.x, a0.y, a0.z, a0.w, a1.x, a1.y, a1.z, a1.w};
#pragma unroll
            for (int u = 0; u < 8; u++) p[u] = __expf(p[u] - mrow) * inv;
            w0 = make_float4(p[0], p[1], p[2], p[3]);
            w1 = make_float4(p[4], p[5], p[6], p[7]);
            *(float4*)(Aptr + k0 + 16) = w0;
            *(float4*)(Aptr + k0 + 20) = w1;
        }
#pragma unroll
        for (int kk = 0; kk < 16; kk++) {
            float4 av0 = *(const float4*)&As[buf][kk][ty * 8];
            float4 av1 = *(const float4*)&As[buf][kk][ty * 8 + 4];
            float4 bv  = *(const float4*)&Bs[buf][kk][tx * 4];
            float a[8] = {av0.x, av0.y, av0.z, av0.w, av1.x, av1.y, av1.z, av1.w};
            float bb[4] = {bv.x, bv.y, bv.z, bv.w};
#pragma unroll
            for (int i = 0; i < 8; i++)
#pragma unroll
                for (int j = 0; j < 4; j++)
                    acc[i][j] += a[i] * bb[j];
        }
        if (more) {
            buf ^= 1;
            stg_smem_t(As[buf], ak, arow, w0, w1);
            *(float4*)&Bs[buf][brow][bcol] = nb;
            __syncthreads();
        }
    }

#pragma unroll
    for (int i = 0; i < 8; i++) {
        int row = bm + ty * 8 + i;
        float4 o = {acc[i][0], acc[i][1], acc[i][2], acc[i][3]};
        *(float4*)(C + (size_t)row * E_ + tx * 4) = o;
    }
}

// ---------------------------------------------------------------------------
extern "C" void kernel_launch(void* const* d_in, const int* in_sizes, int n_in,
                              void* d_out, int out_size)
{
    const float* q    = (const float*)d_in[0];
    const float* k    = (const float*)d_in[1];
    const float* v    = (const float*)d_in[2];
    const int*   mask = (const int*)d_in[3];
    const float* Wq   = (const float*)d_in[4];
    const float* bq   = (const float*)d_in[5];
    const float* Wk   = (const float*)d_in[6];
    const float* bk   = (const float*)d_in[7];
    const float* Wv   = (const float*)d_in[8];
    const float* bv   = (const float*)d_in[9];
    const float* Wo   = (const float*)d_in[10];
    const float* bo   = (const float*)d_in[11];

    float* out  = (float*)d_out;                  // [B,T,E]
    float* attn = out + (size_t)B_ * T_ * E_;     // [B,H,T,S]

    float *Qp, *Kp, *Vp, *Ctx;
    float2 *part, *stats;
    cudaGetSymbolAddress((void**)&Qp, g_Qp);
    cudaGetSymbolAddress((void**)&Kp, g_Kp);
    cudaGetSymbolAddress((void**)&Vp, g_Vp);
    cudaGetSymbolAddress((void**)&Ctx, g_ctx);
    cudaGetSymbolAddress((void**)&part, g_part);
    cudaGetSymbolAddress((void**)&stats, g_stats);

    dim3 blk(256);
    dim3 gproj(E_ / 128, (B_ * T_) / 128);        // 8 x 32

    gemm_nt_bias<<<gproj, blk>>>(q, Wq, bq, Qp, E_, E_, E_, E_, SCALE_);
    gemm_nt_bias<<<gproj, blk>>>(k, Wk, bk, Kp, E_, E_, E_, E_, 1.0f);
    gemm_nt_bias<<<gproj, blk>>>(v, Wv, bv, Vp, E_, E_, E_, E_, 1.0f);

    attn_scores<<<dim3(S_ / 128, T_ / 128, B_ * H_), blk>>>(Qp, Kp, mask, attn, part);

    stats_reduce<<<(B_ * H_ * T_) / 256, blk>>>(part, stats);

    attn_pv<<<dim3(1, T_ / 128, B_ * H_), blk>>>(attn, Vp, stats, Ctx);

    gemm_nt_bias<<<gproj, blk>>>(Ctx, Wo, bo, out, E_, E_, E_, E_, 1.0f);
}

// round 3
// speedup vs baseline: 1.8173x; 1.6552x over previous
#include <cuda_runtime.h>
#include <math.h>

#define B_   2
#define T_   2048
#define S_   2048
#define E_   1024
#define H_   16
#define DH_  64
#define SCALE_ 0.125f
#define CLAMP_V 50000.0f
#define NBLK 16              // S_/128 score col-blocks per row

// Scratch (device globals: no allocations allowed)
__device__ float  g_Qp[B_ * T_ * E_];
__device__ float  g_Kp[B_ * S_ * E_];
__device__ float  g_Vp[B_ * S_ * E_];
__device__ float  g_ctx[B_ * T_ * E_];
__device__ float2 g_part[(size_t)B_ * H_ * T_ * NBLK];
__device__ float2 g_stats[(size_t)B_ * H_ * T_];

// ---------------------------------------------------------------------------
__device__ __forceinline__ unsigned cvt_tf32(float x) {
    unsigned r;
    asm("cvt.rna.tf32.f32 %0, %1;" : "=r"(r) : "f"(x));
    return r;
}

__device__ __forceinline__ void mma8(float* d, const unsigned* a, const unsigned* b) {
    asm volatile(
        "mma.sync.aligned.m16n8k8.row.col.f32.tf32.tf32.f32 "
        "{%0,%1,%2,%3}, {%4,%5,%6,%7}, {%8,%9}, {%0,%1,%2,%3};"
        : "+f"(d[0]), "+f"(d[1]), "+f"(d[2]), "+f"(d[3])
        : "r"(a[0]), "r"(a[1]), "r"(a[2]), "r"(a[3]), "r"(b[0]), "r"(b[1]));
}

// store 8 k-consecutive values (tf32-rounded) k-major: Sm[k][row]
__device__ __forceinline__ void stg8(float (*Sm)[136], int kb, int row,
                                     float4 v0, float4 v1) {
    Sm[kb + 0][row] = __uint_as_float(cvt_tf32(v0.x));
    Sm[kb + 1][row] = __uint_as_float(cvt_tf32(v0.y));
    Sm[kb + 2][row] = __uint_as_float(cvt_tf32(v0.z));
    Sm[kb + 3][row] = __uint_as_float(cvt_tf32(v0.w));
    Sm[kb + 4][row] = __uint_as_float(cvt_tf32(v1.x));
    Sm[kb + 5][row] = __uint_as_float(cvt_tf32(v1.y));
    Sm[kb + 6][row] = __uint_as_float(cvt_tf32(v1.z));
    Sm[kb + 7][row] = __uint_as_float(cvt_tf32(v1.w));
}

__device__ __forceinline__ void softmax_merge(float& m, float& s, float om, float os) {
    float nm = fmaxf(m, om);
    if (nm == -INFINITY) { m = nm; s = 0.f; return; }
    s = s * __expf(m - nm) + os * __expf(om - nm);
    m = nm;
}

// ---------------------------------------------------------------------------
// NT GEMM + bias + alpha, tf32 tensor cores.
// BM=BN=128, BK=16, 256 thr = 8 warps (2m x 4n), warp tile 64x32.
// ---------------------------------------------------------------------------
__global__ __launch_bounds__(256) void gemm_nt_bias(
    const float* __restrict__ A, const float* __restrict__ Bm,
    const float* __restrict__ bias, float* __restrict__ C,
    int K, int lda, int ldb, int ldc, float alpha)
{
    __shared__ float As[2][16][136];
    __shared__ float Bs[2][16][136];
    const int tid = threadIdx.x;
    const int lane = tid & 31, w = tid >> 5;
    const int wm = w & 1, wn = w >> 1;
    const int lr = lane >> 2, lc = lane & 3;
    const int bm = blockIdx.y * 128, bn = blockIdx.x * 128;
    const int lrow = tid >> 1, lk = (tid & 1) * 8;

    const float* Ap = A + (size_t)(bm + lrow) * lda + lk;
    const float* Bp = Bm + (size_t)(bn + lrow) * ldb + lk;

    float acc[4][4][4] = {};

    {
        float4 a0 = *(const float4*)(Ap);
        float4 a1 = *(const float4*)(Ap + 4);
        float4 b0 = *(const float4*)(Bp);
        float4 b1 = *(const float4*)(Bp + 4);
        stg8(As[0], lk, lrow, a0, a1);
        stg8(Bs[0], lk, lrow, b0, b1);
    }
    __syncthreads();

    int buf = 0;
    for (int k0 = 0; k0 < K; k0 += 16) {
        const bool more = (k0 + 16) < K;
        float4 na0, na1, nb0, nb1;
        if (more) {
            na0 = *(const float4*)(Ap + k0 + 16);
            na1 = *(const float4*)(Ap + k0 + 20);
            nb0 = *(const float4*)(Bp + k0 + 16);
            nb1 = *(const float4*)(Bp + k0 + 20);
        }
#pragma unroll
        for (int kt = 0; kt < 2; kt++) {
            const int kk = kt * 8;
            unsigned af[4][4], bf[4][2];
#pragma unroll
            for (int i = 0; i < 4; i++) {
                int mb = wm * 64 + i * 16 + lr;
                af[i][0] = __float_as_uint(As[buf][kk + lc][mb]);
                af[i][1] = __float_as_uint(As[buf][kk + lc][mb + 8]);
                af[i][2] = __float_as_uint(As[buf][kk + 4 + lc][mb]);
                af[i][3] = __float_as_uint(As[buf][kk + 4 + lc][mb + 8]);
            }
#pragma unroll
            for (int j = 0; j < 4; j++) {
                int nb = wn * 32 + j * 8 + lr;
                bf[j][0] = __float_as_uint(Bs[buf][kk + lc][nb]);
                bf[j][1] = __float_as_uint(Bs[buf][kk + 4 + lc][nb]);
            }
#pragma unroll
            for (int i = 0; i < 4; i++)
#pragma unroll
                for (int j = 0; j < 4; j++)
                    mma8(acc[i][j], af[i], bf[j]);
        }
        if (more) {
            buf ^= 1;
            stg8(As[buf], lk, lrow, na0, na1);
            stg8(Bs[buf], lk, lrow, nb0, nb1);
            __syncthreads();
        }
    }

#pragma unroll
    for (int j = 0; j < 4; j++) {
        int col = bn + wn * 32 + j * 8 + lc * 2;
        float b0v = bias[col], b1v = bias[col + 1];
#pragma unroll
        for (int i = 0; i < 4; i++) {
            int row = bm + wm * 64 + i * 16 + lr;
            float2 lo = {alpha * (acc[i][j][0] + b0v), alpha * (acc[i][j][1] + b1v)};
            float2 hi = {alpha * (acc[i][j][2] + b0v), alpha * (acc[i][j][3] + b1v)};
            *(float2*)(C + (size_t)row * ldc + col)       = lo;
            *(float2*)(C + (size_t)(row + 8) * ldc + col) = hi;
        }
    }
}

// ---------------------------------------------------------------------------
// Scores: per (b,h) 128x128 tile: clamp(Q.K^T), mask->-inf, write raw P,
// emit per-(row, 128colblk) softmax partials. tf32 tensor cores, K=64.
// ---------------------------------------------------------------------------
__global__ __launch_bounds__(256) void attn_scores(
    const float* __restrict__ Qp, const float* __restrict__ Kp,
    const int* __restrict__ mask, float* __restrict__ P,
    float2* __restrict__ part)
{
    __shared__ float As[2][16][136];
    __shared__ float Bs[2][16][136];
    __shared__ float2 red[4][128];
    __shared__ int msk[128];

    const int bh = blockIdx.z;
    const int b  = bh >> 4;
    const int h  = bh & 15;
    const float* A  = Qp + (size_t)b * T_ * E_ + h * DH_;
    const float* Bm = Kp + (size_t)b * S_ * E_ + h * DH_;
    float* C = P + (size_t)bh * T_ * S_;

    const int tid = threadIdx.x;
    const int lane = tid & 31, w = tid >> 5;
    const int wm = w & 1, wn = w >> 1;
    const int lr = lane >> 2, lc = lane & 3;
    const int bm = blockIdx.y * 128, bn = blockIdx.x * 128;
    const int lrow = tid >> 1, lk = (tid & 1) * 8;

    const float* Ap = A + (size_t)(bm + lrow) * E_ + lk;
    const float* Bp = Bm + (size_t)(bn + lrow) * E_ + lk;

    float acc[4][4][4] = {};

    if (tid < 128) msk[tid] = mask[(size_t)b * S_ + bn + tid];
    {
        float4 a0 = *(const float4*)(Ap);
        float4 a1 = *(const float4*)(Ap + 4);
        float4 b0 = *(const float4*)(Bp);
        float4 b1 = *(const float4*)(Bp + 4);
        stg8(As[0], lk, lrow, a0, a1);
        stg8(Bs[0], lk, lrow, b0, b1);
    }
    __syncthreads();

    int buf = 0;
    for (int k0 = 0; k0 < DH_; k0 += 16) {
        const bool more = (k0 + 16) < DH_;
        float4 na0, na1, nb0, nb1;
        if (more) {
            na0 = *(const float4*)(Ap + k0 + 16);
            na1 = *(const float4*)(Ap + k0 + 20);
            nb0 = *(const float4*)(Bp + k0 + 16);
            nb1 = *(const float4*)(Bp + k0 + 20);
        }
#pragma unroll
        for (int kt = 0; kt < 2; kt++) {
            const int kk = kt * 8;
            unsigned af[4][4], bf[4][2];
#pragma unroll
            for (int i = 0; i < 4; i++) {
                int mb = wm * 64 + i * 16 + lr;
                af[i][0] = __float_as_uint(As[buf][kk + lc][mb]);
                af[i][1] = __float_as_uint(As[buf][kk + lc][mb + 8]);
                af[i][2] = __float_as_uint(As[buf][kk + 4 + lc][mb]);
                af[i][3] = __float_as_uint(As[buf][kk + 4 + lc][mb + 8]);
            }
#pragma unroll
            for (int j = 0; j < 4; j++) {
                int nb = wn * 32 + j * 8 + lr;
                bf[j][0] = __float_as_uint(Bs[buf][kk + lc][nb]);
                bf[j][1] = __float_as_uint(Bs[buf][kk + 4 + lc][nb]);
            }
#pragma unroll
            for (int i = 0; i < 4; i++)
#pragma unroll
                for (int j = 0; j < 4; j++)
                    mma8(acc[i][j], af[i], bf[j]);
        }
        if (more) {
            buf ^= 1;
            stg8(As[buf], lk, lrow, na0, na1);
            stg8(Bs[buf], lk, lrow, nb0, nb1);
            __syncthreads();
        }
    }

    // epilogue: clamp + mask + store raw + per-row partial (m, s)
#pragma unroll
    for (int i = 0; i < 4; i++) {
        int rloc_lo = wm * 64 + i * 16 + lr;
        int rloc_hi = rloc_lo + 8;
        float m_lo = -INFINITY, m_hi = -INFINITY;
        float vlo[4][2], vhi[4][2];
#pragma unroll
        for (int j = 0; j < 4; j++) {
            int lcol = wn * 32 + j * 8 + lc * 2;
            bool k0m = msk[lcol] != 0;
            bool k1m = msk[lcol + 1] != 0;
            float a0 = fminf(fmaxf(acc[i][j][0], -CLAMP_V), CLAMP_V);
            float a1 = fminf(fmaxf(acc[i][j][1], -CLAMP_V), CLAMP_V);
            float a2 = fminf(fmaxf(acc[i][j][2], -CLAMP_V), CLAMP_V);
            float a3 = fminf(fmaxf(acc[i][j][3], -CLAMP_V), CLAMP_V);
            vlo[j][0] = k0m ? a0 : -INFINITY;
            vlo[j][1] = k1m ? a1 : -INFINITY;
            vhi[j][0] = k0m ? a2 : -INFINITY;
            vhi[j][1] = k1m ? a3 : -INFINITY;
            m_lo = fmaxf(m_lo, fmaxf(vlo[j][0], vlo[j][1]));
            m_hi = fmaxf(m_hi, fmaxf(vhi[j][0], vhi[j][1]));
            int col = bn + lcol;
            *(float2*)(C + (size_t)(bm + rloc_lo) * S_ + col) = make_float2(vlo[j][0], vlo[j][1]);
            *(float2*)(C + (size_t)(bm + rloc_hi) * S_ + col) = make_float2(vhi[j][0], vhi[j][1]);
        }
        float s_lo = 0.f, s_hi = 0.f;
        if (m_lo != -INFINITY) {
#pragma unroll
            for (int j = 0; j < 4; j++)
                s_lo += __expf(vlo[j][0] - m_lo) + __expf(vlo[j][1] - m_lo);
        }
        if (m_hi != -INFINITY) {
#pragma unroll
            for (int j = 0; j < 4; j++)
                s_hi += __expf(vhi[j][0] - m_hi) + __expf(vhi[j][1] - m_hi);
        }
#pragma unroll
        for (int off = 1; off <= 2; off <<= 1) {
            softmax_merge(m_lo, s_lo, __shfl_xor_sync(0xffffffffu, m_lo, off),
                                      __shfl_xor_sync(0xffffffffu, s_lo, off));
            softmax_merge(m_hi, s_hi, __shfl_xor_sync(0xffffffffu, m_hi, off),
                                      __shfl_xor_sync(0xffffffffu, s_hi, off));
        }
        if (lc == 0) {
            red[wn][rloc_lo] = make_float2(m_lo, s_lo);
            red[wn][rloc_hi] = make_float2(m_hi, s_hi);
        }
    }
    __syncthreads();
    if (tid < 128) {
        float m = -INFINITY, s = 0.f;
#pragma unroll
        for (int j = 0; j < 4; j++) {
            float2 p = red[j][tid];
            softmax_merge(m, s, p.x, p.y);
        }
        part[((size_t)bh * T_ + bm + tid) * NBLK + blockIdx.x] = make_float2(m, s);
    }
}

// ---------------------------------------------------------------------------
__global__ __launch_bounds__(256) void stats_reduce(
    const float2* __restrict__ part, float2* __restrict__ stats)
{
    int r = blockIdx.x * 256 + threadIdx.x;
    float m = -INFINITY, s = 0.f;
#pragma unroll
    for (int j = 0; j < NBLK; j++) {
        float2 p = part[(size_t)r * NBLK + j];
        softmax_merge(m, s, p.x, p.y);
    }
    stats[r] = make_float2(m, 1.f / s);
}

// ---------------------------------------------------------------------------
// PV: reads raw scores, p = exp(v-m)*inv, writes normalized P + Ctx = P@V.
// BM=128, BN=64, BK=16, 8 warps (2m x 4n), warp tile 64x16. tf32 mma.
// ---------------------------------------------------------------------------
__global__ __launch_bounds__(256) void attn_pv(
    float* __restrict__ P, const float* __restrict__ Vp,
    const float2* __restrict__ stats, float* __restrict__ Ctx)
{
    __shared__ float As[2][16][136];
    __shared__ float Bs[2][16][72];
    const int bh = blockIdx.z;
    const int b  = bh >> 4;
    const int h  = bh & 15;
    float* A = P + (size_t)bh * T_ * S_;
    const float* Bm = Vp + (size_t)b * S_ * E_ + h * DH_;
    float* C = Ctx + (size_t)b * T_ * E_ + h * DH_;

    const int tid = threadIdx.x;
    const int lane = tid & 31, w = tid >> 5;
    const int wm = w & 1, wn = w >> 1;
    const int lr = lane >> 2, lc = lane & 3;
    const int bm = blockIdx.y * 128;
    const int arow = tid >> 1, ak = (tid & 1) * 8;
    const int brow = tid >> 4, bcol = (tid & 15) * 4;

    float* Aptr = A + (size_t)(bm + arow) * S_ + ak;
    const float* Bptr = Bm + (size_t)brow * E_ + bcol;

    float2 st = stats[(size_t)bh * T_ + bm + arow];
    const float mrow = st.x, inv = st.y;

    float acc[4][2][4] = {};

    {
        float4 a0 = *(const float4*)(Aptr);
        float4 a1 = *(const float4*)(Aptr + 4);
        float4 b4 = *(const float4*)(Bptr);
        float p[8] = {a0.x, a0.y, a0.z, a0.w, a1.x, a1.y, a1.z, a1.w};
#pragma unroll
        for (int u = 0; u < 8; u++) p[u] = __expf(p[u] - mrow) * inv;
        float4 w0 = {p[0], p[1], p[2], p[3]};
        float4 w1 = {p[4], p[5], p[6], p[7]};
        *(float4*)(Aptr)     = w0;
        *(float4*)(Aptr + 4) = w1;
        stg8(As[0], ak, arow, w0, w1);
        Bs[0][brow][bcol + 0] = __uint_as_float(cvt_tf32(b4.x));
        Bs[0][brow][bcol + 1] = __uint_as_float(cvt_tf32(b4.y));
        Bs[0][brow][bcol + 2] = __uint_as_float(cvt_tf32(b4.z));
        Bs[0][brow][bcol + 3] = __uint_as_float(cvt_tf32(b4.w));
    }
    __syncthreads();

    int buf = 0;
    for (int k0 = 0; k0 < S_; k0 += 16) {
        const bool more = (k0 + 16) < S_;
        float4 w0, w1, nb;
        if (more) {
            float4 a0 = *(const float4*)(Aptr + k0 + 16);
            float4 a1 = *(const float4*)(Aptr + k0 + 20);
            nb = *(const float4*)(Bptr + (size_t)(k0 + 16) * E_);
            float p[8] = {a0.x, a0.y, a0.z, a0.w, a1.x, a1.y, a1.z, a1.w};
#pragma unroll
            for (int u = 0; u < 8; u++) p[u] = __expf(p[u] - mrow) * inv;
            w0 = make_float4(p[0], p[1], p[2], p[3]);
            w1 = make_float4(p[4], p[5], p[6], p[7]);
            *(float4*)(Aptr + k0 + 16) = w0;
            *(float4*)(Aptr + k0 + 20) = w1;
        }
#pragma unroll
        for (int kt = 0; kt < 2; kt++) {
            const int kk = kt * 8;
            unsigned af[4][4], bf[2][2];
#pragma unroll
            for (int i = 0; i < 4; i++) {
                int mb = wm * 64 + i * 16 + lr;
                af[i][0] = __float_as_uint(As[buf][kk + lc][mb]);
                af[i][1] = __float_as_uint(As[buf][kk + lc][mb + 8]);
                af[i][2] = __float_as_uint(As[buf][kk + 4 + lc][mb]);
                af[i][3] = __float_as_uint(As[buf][kk + 4 + lc][mb + 8]);
            }
#pragma unroll
            for (int j = 0; j < 2; j++) {
                int nb2 = wn * 16 + j * 8 + lr;
                bf[j][0] = __float_as_uint(Bs[buf][kk + lc][nb2]);
                bf[j][1] = __float_as_uint(Bs[buf][kk + 4 + lc][nb2]);
            }
#pragma unroll
            for (int i = 0; i < 4; i++)
#pragma unroll
                for (int j = 0; j < 2; j++)
                    mma8(acc[i][j], af[i], bf[j]);
        }
        if (more) {
            buf ^= 1;
            stg8(As[buf], ak, arow, w0, w1);
            Bs[buf][brow][bcol + 0] = __uint_as_float(cvt_tf32(nb.x));
            Bs[buf][brow][bcol + 1] = __uint_as_float(cvt_tf32(nb.y));
            Bs[buf][brow][bcol + 2] = __uint_as_float(cvt_tf32(nb.z));
            Bs[buf][brow][bcol + 3] = __uint_as_float(cvt_tf32(nb.w));
            __syncthreads();
        }
    }

#pragma unroll
    for (int j = 0; j < 2; j++) {
        int col = wn * 16 + j * 8 + lc * 2;
#pragma unroll
        for (int i = 0; i < 4; i++) {
            int row = bm + wm * 64 + i * 16 + lr;
            *(float2*)(C + (size_t)row * E_ + col)       = make_float2(acc[i][j][0], acc[i][j][1]);
            *(float2*)(C + (size_t)(row + 8) * E_ + col) = make_float2(acc[i][j][2], acc[i][j][3]);
        }
    }
}

// ---------------------------------------------------------------------------
extern "C" void kernel_launch(void* const* d_in, const int* in_sizes, int n_in,
                              void* d_out, int out_size)
{
    const float* q    = (const float*)d_in[0];
    const float* k    = (const float*)d_in[1];
    const float* v    = (const float*)d_in[2];
    const int*   mask = (const int*)d_in[3];
    const float* Wq   = (const float*)d_in[4];
    const float* bq   = (const float*)d_in[5];
    const float* Wk   = (const float*)d_in[6];
    const float* bk   = (const float*)d_in[7];
    const float* Wv   = (const float*)d_in[8];
    const float* bv   = (const float*)d_in[9];
    const float* Wo   = (const float*)d_in[10];
    const float* bo   = (const float*)d_in[11];

    float* out  = (float*)d_out;
    float* attn = out + (size_t)B_ * T_ * E_;

    float *Qp, *Kp, *Vp, *Ctx;
    float2 *part, *stats;
    cudaGetSymbolAddress((void**)&Qp, g_Qp);
    cudaGetSymbolAddress((void**)&Kp, g_Kp);
    cudaGetSymbolAddress((void**)&Vp, g_Vp);
    cudaGetSymbolAddress((void**)&Ctx, g_ctx);
    cudaGetSymbolAddress((void**)&part, g_part);
    cudaGetSymbolAddress((void**)&stats, g_stats);

    dim3 blk(256);
    dim3 gproj(E_ / 128, (B_ * T_) / 128);

    gemm_nt_bias<<<gproj, blk>>>(q, Wq, bq, Qp, E_, E_, E_, E_, SCALE_);
    gemm_nt_bias<<<gproj, blk>>>(k, Wk, bk, Kp, E_, E_, E_, E_, 1.0f);
    gemm_nt_bias<<<gproj, blk>>>(v, Wv, bv, Vp, E_, E_, E_, E_, 1.0f);

    attn_scores<<<dim3(S_ / 128, T_ / 128, B_ * H_), blk>>>(Qp, Kp, mask, attn, part);

    stats_reduce<<<(B_ * H_ * T_) / 256, blk>>>(part, stats);

    attn_pv<<<dim3(1, T_ / 128, B_ * H_), blk>>>(attn, Vp, stats, Ctx);

    gemm_nt_bias<<<gproj, blk>>>(Ctx, Wo, bo, out, E_, E_, E_, E_, 1.0f);
}